// round 12
// baseline (speedup 1.0000x reference)
#include <cuda_runtime.h>
#include <cuda_fp16.h>
#include <cstdint>
#include <cstddef>

#define EPSRMS 1.1920929e-07f

// ---------------- persistent device scratch ----------------
__device__ __half g_z [16777216];          // rmsnorm output (fp16)
__device__ float  g_h0[16777216];
__device__ float  g_h1[16777216];
__device__ __half g_P [16384*64];
__device__ __half g_Pp[16384*32];
__device__ __half g_ff[16384*2816];        // silu(ffg)*fff (fp16)
__device__ float  g_part[8*16384*64];
__device__ __half g_wh[2170880];           // fp16 weight copies

// weight offsets inside g_wh (element counts)
#define W_FGW  0
#define W_GUW  262144
#define W_FGA  524288
#define W_GUA  557056
#define W_FGB  589824
#define W_GUB  655360
#define W_FFGW 720896
#define W_FFGA 1081344
#define W_FFGB 1171456
#define W_FFFW 1204224
#define W_FFFA 1564672
#define W_FFFB 1654784
#define W_FFPW 1687552
#define W_FFPA 2048000
#define W_FFPB 2080768

// ---------------- helpers ----------------
__device__ __forceinline__ float sigm(float x){ return 1.0f/(1.0f+__expf(-x)); }

__device__ __forceinline__ uint32_t smem_u32(const void* p){
    uint32_t a;
    asm("{ .reg .u64 t; cvta.to.shared.u64 t, %1; cvt.u32.u64 %0, t; }" : "=r"(a) : "l"(p));
    return a;
}

__device__ __forceinline__ void mma16(float4& d, uint4 a, uint2 b){
    asm volatile(
        "mma.sync.aligned.m16n8k16.row.col.f32.f16.f16.f32 "
        "{%0,%1,%2,%3},{%4,%5,%6,%7},{%8,%9},{%0,%1,%2,%3};"
        : "+f"(d.x), "+f"(d.y), "+f"(d.z), "+f"(d.w)
        : "r"(a.x), "r"(a.y), "r"(a.z), "r"(a.w), "r"(b.x), "r"(b.y));
}

__device__ __forceinline__ void ldsm_x4(uint4& r, uint32_t a){
    asm volatile("ldmatrix.sync.aligned.m8n8.x4.shared.b16 {%0,%1,%2,%3}, [%4];"
                 : "=r"(r.x), "=r"(r.y), "=r"(r.z), "=r"(r.w) : "r"(a));
}
__device__ __forceinline__ void ldsm_x2(uint2& r, uint32_t a){
    asm volatile("ldmatrix.sync.aligned.m8n8.x2.shared.b16 {%0,%1}, [%2];"
                 : "=r"(r.x), "=r"(r.y) : "r"(a));
}

__device__ __forceinline__ void cp16(uint32_t dst, const void* src, int sz){
    asm volatile("cp.async.ca.shared.global [%0], [%1], 16, %2;"
                 :: "r"(dst), "l"(src), "r"(sz) : "memory");
}
#define CPCOMMIT() asm volatile("cp.async.commit_group;" ::: "memory")
#define CPWAIT0()  asm volatile("cp.async.wait_group 0;"  ::: "memory")

// ---------------- smem staging (rows of 128B = 64 fp16, XOR-swizzled 16B chunks) ----------
template<int NCHUNK>
__device__ __forceinline__ void stage_tile(uint32_t sb, const __half* src, size_t ld){
    int tid = threadIdx.x;
    #pragma unroll
    for (int i = 0; i < (NCHUNK + 255)/256; i++){
        int idx = tid + i*256;
        if ((NCHUNK & 255) && idx >= NCHUNK) continue;
        int r = idx >> 3, c4 = idx & 7;
        cp16(sb + r*128 + ((uint32_t)(c4 ^ (r & 7)) << 4),
             src + (size_t)r*ld + (c4 << 3), 16);
    }
}

template<int NCHUNK>
__device__ __forceinline__ void stage_tile_vc(uint32_t sb, const __half* src, size_t ld, int vc){
    int tid = threadIdx.x;
    #pragma unroll
    for (int i = 0; i < (NCHUNK + 255)/256; i++){
        int idx = tid + i*256;
        if ((NCHUNK & 255) && idx >= NCHUNK) continue;
        int r = idx >> 3, c4 = idx & 7;
        int ok = (c4 < vc);
        cp16(sb + r*128 + ((uint32_t)(c4 ^ (r & 7)) << 4),
             src + (size_t)r*ld + ((ok ? c4 : 0) << 3), ok ? 16 : 0);
    }
}

__device__ __forceinline__ void stage_tok(uint32_t sb, const __half* zb,
                                          int seq0, int shift, int col){
    int tid = threadIdx.x;
    #pragma unroll
    for (int i = 0; i < 4; i++){
        int idx = tid + i*256;
        int r = idx >> 3, c4 = idx & 7;
        int s = seq0 + r - shift;
        int sz = (s >= 0) ? 16 : 0;
        if (s < 0) s = 0;
        cp16(sb + r*128 + ((uint32_t)(c4 ^ (r & 7)) << 4),
             zb + (size_t)s*1024 + col + (c4 << 3), sz);
    }
}

// ---------------- fp16 ldmatrix fragment compute over one K=64 slab ----------------
template<int MT, int NT>
__device__ __forceinline__ void compLh(uint32_t sAu, uint32_t sBu, float4* acc,
                                       int mb0, int nb0, int lane){
    const int arow = (lane & 7) + ((lane >> 3) & 1)*8;
    const int khA  = (lane >> 4) & 1;
    uint32_t aB[MT]; int asw[MT];
    #pragma unroll
    for (int m = 0; m < MT; m++){
        int r = mb0 + m*16 + arow;
        aB[m] = sAu + r*128; asw[m] = r & 7;
    }
    constexpr int NP = NT >> 1;
    const int brow = ((lane >> 4) & 1)*8 + (lane & 7);
    const int khB  = (lane >> 3) & 1;
    uint32_t bB[NP > 0 ? NP : 1]; int bsw[NP > 0 ? NP : 1];
    #pragma unroll
    for (int p = 0; p < NP; p++){
        int r = nb0 + p*16 + brow;
        bB[p] = sBu + r*128; bsw[p] = r & 7;
    }
    uint32_t oB = 0; int osw = 0;
    if constexpr (NT & 1){
        int r = nb0 + (NT-1)*8 + (lane & 7);
        oB = sBu + r*128; osw = r & 7;
    }
    const int khO = (lane >> 3) & 1;
    #pragma unroll
    for (int kc = 0; kc < 4; kc++){
        uint4 a[MT];
        #pragma unroll
        for (int m = 0; m < MT; m++)
            ldsm_x4(a[m], aB[m] + (uint32_t)((((kc<<1)|khA) ^ asw[m]) << 4));
        #pragma unroll
        for (int p = 0; p < NP; p++){
            uint4 b;
            ldsm_x4(b, bB[p] + (uint32_t)((((kc<<1)|khB) ^ bsw[p]) << 4));
            #pragma unroll
            for (int m = 0; m < MT; m++){
                mma16(acc[m*NT + 2*p    ], a[m], make_uint2(b.x, b.y));
                mma16(acc[m*NT + 2*p + 1], a[m], make_uint2(b.z, b.w));
            }
        }
        if constexpr (NT & 1){
            uint2 b;
            ldsm_x2(b, oB + (uint32_t)((((kc<<1)|khO) ^ osw) << 4));
            #pragma unroll
            for (int m = 0; m < MT; m++)
                mma16(acc[m*NT + NT - 1], a[m], b);
        }
    }
}

template<int MT, int NT>
__device__ __forceinline__ void compL2h(uint32_t sAu, uint32_t sB1, uint32_t sB2,
                                        float4* acc1, float4* acc2,
                                        int mb0, int nb0, int lane){
    static_assert((NT & 1) == 0, "NT even");
    const int arow = (lane & 7) + ((lane >> 3) & 1)*8;
    const int khA  = (lane >> 4) & 1;
    uint32_t aB[MT]; int asw[MT];
    #pragma unroll
    for (int m = 0; m < MT; m++){
        int r = mb0 + m*16 + arow;
        aB[m] = sAu + r*128; asw[m] = r & 7;
    }
    constexpr int NP = NT >> 1;
    const int brow = ((lane >> 4) & 1)*8 + (lane & 7);
    const int khB  = (lane >> 3) & 1;
    uint32_t b1B[NP], b2B[NP]; int bsw[NP];
    #pragma unroll
    for (int p = 0; p < NP; p++){
        int r = nb0 + p*16 + brow;
        b1B[p] = sB1 + r*128; b2B[p] = sB2 + r*128; bsw[p] = r & 7;
    }
    #pragma unroll
    for (int kc = 0; kc < 4; kc++){
        uint4 a[MT];
        #pragma unroll
        for (int m = 0; m < MT; m++)
            ldsm_x4(a[m], aB[m] + (uint32_t)((((kc<<1)|khA) ^ asw[m]) << 4));
        #pragma unroll
        for (int p = 0; p < NP; p++){
            uint32_t off = (uint32_t)((((kc<<1)|khB) ^ bsw[p]) << 4);
            uint4 b1, b2;
            ldsm_x4(b1, b1B[p] + off);
            ldsm_x4(b2, b2B[p] + off);
            #pragma unroll
            for (int m = 0; m < MT; m++){
                mma16(acc1[m*NT + 2*p    ], a[m], make_uint2(b1.x, b1.y));
                mma16(acc1[m*NT + 2*p + 1], a[m], make_uint2(b1.z, b1.w));
                mma16(acc2[m*NT + 2*p    ], a[m], make_uint2(b2.x, b2.y));
                mma16(acc2[m*NT + 2*p + 1], a[m], make_uint2(b2.z, b2.w));
            }
        }
    }
}

// ---------------- weight fp16 conversion ----------------
__global__ void cvt_k(const float* p0, const float* p1, const float* p2, const float* p3,
                      const float* p4, const float* p5, const float* p6, const float* p7,
                      const float* p8, const float* p9, const float* p10, const float* p11,
                      const float* p12, const float* p13, const float* p14){
    const float* srcs[15] = {p0,p1,p2,p3,p4,p5,p6,p7,p8,p9,p10,p11,p12,p13,p14};
    const int sz4[15] = {65536,65536,8192,8192,16384,16384,90112,22528,8192,
                         90112,22528,8192,90112,8192,22528};
    const int off[15] = {W_FGW,W_GUW,W_FGA,W_GUA,W_FGB,W_GUB,W_FFGW,W_FFGA,W_FFGB,
                         W_FFFW,W_FFFA,W_FFFB,W_FFPW,W_FFPA,W_FFPB};
    int t = blockIdx.y;
    int i = blockIdx.x*256 + threadIdx.x;
    if (i >= sz4[t]) return;
    float4 v = ((const float4*)srcs[t])[i];
    __half2* dst = (__half2*)(g_wh + off[t]);
    dst[2*i]     = __floats2half2_rn(v.x, v.y);
    dst[2*i + 1] = __floats2half2_rn(v.z, v.w);
}

// ---------------- rmsnorm: h -> z (fp16 output) ----------------
__global__ __launch_bounds__(256)
void rms_k(const float* __restrict__ h, __half* __restrict__ z){
    int warp = threadIdx.x >> 5, lane = threadIdx.x & 31;
    size_t tok = (size_t)blockIdx.x*8 + warp;
    const float4* hr = (const float4*)(h + tok*1024);
    float4 v[8]; float ss = 0.f;
    #pragma unroll
    for (int j = 0; j < 8; j++){
        v[j] = hr[lane + 32*j];
        ss += v[j].x*v[j].x + v[j].y*v[j].y + v[j].z*v[j].z + v[j].w*v[j].w;
    }
    #pragma unroll
    for (int o = 16; o; o >>= 1) ss += __shfl_xor_sync(0xffffffffu, ss, o);
    float sc = rsqrtf(ss*(1.f/1024.f) + EPSRMS);
    __half2* zr = (__half2*)(z + tok*1024);
    #pragma unroll
    for (int j = 0; j < 8; j++){
        int p = lane + 32*j;
        zr[2*p]     = __floats2half2_rn(v[j].x*sc, v[j].y*sc);
        zr[2*p + 1] = __floats2half2_rn(v[j].z*sc, v[j].w*sc);
    }
}

// ---------------- low-rank projection partials (TP tiles/CTA, B resident) ----------------
__global__ __launch_bounds__(256, 3)
void p_k(const __half* __restrict__ z, const __half* __restrict__ B1,
         const __half* __restrict__ B2, int halves, int ldB, int TP){
    extern __shared__ float sm[];
    uint32_t sb = smem_u32(sm);
    uint32_t SB = sb + 32768u;
    int tid = threadIdx.x, warp = tid >> 5, lane = tid & 31;
    int wm = warp >> 1, wn = warp & 1;
    int chunk = blockIdx.y;
    int half = (halves == 2) ? (chunk >> 2) : 0;
    int colbase = ((halves == 2) ? (chunk & 3) : chunk) << 8;
    int koff = half*1024 + colbase;
    int tile0 = blockIdx.x*TP;

    for (int s = 0; s < 4; s++){
        int ko = koff + (s << 6);
        for (int i = tid; i < 512; i += 256){
            int r = i >> 3, c4 = i & 7;
            const __half* src = ((r < 32) ? B1 : B2) + (size_t)(r & 31)*ldB + ko + (c4 << 3);
            cp16(SB + s*8192u + r*128 + ((uint32_t)(c4 ^ (r & 7)) << 4), src, 16);
        }
    }
    auto fillA = [&](int q){
        int t = q >> 2, s = q & 3;
        int tile = tile0 + t;
        const __half* zb = z + (size_t)(tile >> 4)*2048*1024;
        int seq0 = (tile & 15) << 7;
        stage_tok(sb + (uint32_t)(q & 1)*16384u, zb, seq0, half, colbase + (s << 6));
    };
    fillA(0); CPCOMMIT();

    float4 acc[8];
    #pragma unroll
    for (int i = 0; i < 8; i++) acc[i] = make_float4(0.f,0.f,0.f,0.f);

    int Q = TP*4;
    int lr = lane >> 2, lc2 = (lane & 3)*2;
    for (int q = 0; q < Q; q++){
        CPWAIT0(); __syncthreads();
        if (q + 1 < Q){ fillA(q + 1); CPCOMMIT(); }
        int s = q & 3;
        compLh<2,4>(sb + (uint32_t)(q & 1)*16384u, SB + s*8192u, acc, wm*32, wn*32, lane);
        if (s == 3){
            int tile = tile0 + (q >> 2);
            size_t tok0 = (size_t)tile*128;
            float* dst = g_part + (size_t)chunk*1048576u;
            #pragma unroll
            for (int m = 0; m < 2; m++)
                #pragma unroll
                for (int n = 0; n < 4; n++){
                    int r0 = wm*32 + m*16 + lr;
                    int col = wn*32 + n*8 + lc2;
                    float4 d = acc[m*4 + n];
                    *(float2*)(dst + (tok0 + r0    )*64 + col) = make_float2(d.x, d.y);
                    *(float2*)(dst + (tok0 + r0 + 8)*64 + col) = make_float2(d.z, d.w);
                    acc[m*4 + n] = make_float4(0.f,0.f,0.f,0.f);
                }
        }
    }
}

// reduce partials -> fp16
__global__ void pred_k(__half* __restrict__ dst, const float* __restrict__ src,
                       int nch, size_t cstride, int n4){
    int i = blockIdx.x*256 + threadIdx.x;
    if (i >= n4) return;
    float4 a = ((const float4*)src)[i];
    for (int c = 1; c < nch; c++){
        float4 v = ((const float4*)(src + (size_t)c*cstride))[i];
        a.x += v.x; a.y += v.y; a.z += v.z; a.w += v.w;
    }
    __half2* d2 = (__half2*)dst;
    d2[2*i]     = __floats2half2_rn(a.x, a.y);
    d2[2*i + 1] = __floats2half2_rn(a.z, a.w);
}

// ---------------- iteration main GEMM (2 tiles/CTA, weights resident) ----------------
// grid (64, 16): B: 5 slabs x 16KB resident; A: 2 x 16KB stream.
__global__ __launch_bounds__(256, 2)
void main_k(const __half* __restrict__ z, const __half* __restrict__ P,
            const float* __restrict__ hin, float* __restrict__ hout,
            const __half* __restrict__ Wg, const __half* __restrict__ Wu,
            const __half* __restrict__ Ag, const __half* __restrict__ Au){
    extern __shared__ float sm[];
    uint32_t sb = smem_u32(sm);
    uint32_t SB = sb + 32768u;
    int tid = threadIdx.x, warp = tid >> 5, lane = tid & 31;
    int wm = warp >> 1, wn = warp & 1;
    int nb2 = blockIdx.y;
    int nblk = nb2 >> 1, nh = nb2 & 1;
    int shift = (nblk >= 4) ? 1 : 0;
    int colbase0 = (nblk & 3) << 8;
    int wrow0 = nblk*128 + nh*64;
    int tile0 = blockIdx.x*2;

    for (int s = 0; s < 4; s++){
        const __half* g = Wg + (size_t)wrow0*256 + (s << 6);
        const __half* u = Wu + (size_t)wrow0*256 + (s << 6);
        for (int i = tid; i < 512; i += 256){
            int r = i >> 3, c4 = i & 7;
            uint32_t so = r*128 + ((uint32_t)(c4 ^ (r & 7)) << 4);
            cp16(SB + s*16384u + so,          g + (size_t)r*256 + (c4 << 3), 16);
            cp16(SB + s*16384u + 8192u + so,  u + (size_t)r*256 + (c4 << 3), 16);
        }
    }
    for (int i = tid; i < 512; i += 256){
        int r = i >> 3, c4 = i & 7;
        uint32_t so = r*128 + ((uint32_t)(c4 ^ (r & 7)) << 4);
        int glo = (c4 < 4);
        cp16(SB + 65536u + so,         Ag + (size_t)(wrow0 + r)*32 + ((glo ? c4 : 0) << 3), glo ? 16 : 0);
        cp16(SB + 65536u + 8192u + so, Au + (size_t)(wrow0 + r)*32 + ((glo ? 0 : (c4 - 4)) << 3), glo ? 0 : 16);
    }
    auto fillA = [&](int q){
        int t = q/5, s = q - t*5;
        int tile = tile0 + t;
        const __half* zb = z + (size_t)(tile >> 4)*2048*1024;
        int seq0 = (tile & 15) << 7;
        uint32_t aB = sb + (uint32_t)(q & 1)*16384u;
        if (s < 4) stage_tok(aB, zb, seq0, shift, colbase0 + (s << 6));
        else       stage_tile<1024>(aB, P + (size_t)tile*128*64, 64);
    };
    fillA(0); CPCOMMIT();

    float4 accg[8], accu[8];
    #pragma unroll
    for (int i = 0; i < 8; i++){
        accg[i] = make_float4(0.f,0.f,0.f,0.f);
        accu[i] = make_float4(0.f,0.f,0.f,0.f);
    }

    int lr = lane >> 2, lc2 = (lane & 3)*2;
    for (int q = 0; q < 10; q++){
        CPWAIT0(); __syncthreads();
        if (q + 1 < 10){ fillA(q + 1); CPCOMMIT(); }
        int t = q/5, s = q - t*5;
        compL2h<2,4>(sb + (uint32_t)(q & 1)*16384u,
                     SB + s*16384u, SB + s*16384u + 8192u,
                     accg, accu, wm*32, wn*32, lane);
        if (s == 4){
            size_t tok0 = (size_t)(tile0 + t)*128;
            #pragma unroll
            for (int m = 0; m < 2; m++)
                #pragma unroll
                for (int n = 0; n < 4; n++){
                    int r0 = wm*32 + m*16 + lr;
                    int col = wrow0 + wn*32 + n*8 + lc2;
                    float4 dg = accg[m*4 + n], du = accu[m*4 + n];
                    size_t ta = tok0 + r0, tb = ta + 8;
                    float2 ha = *(const float2*)(hin + ta*1024 + col);
                    float2 hb = *(const float2*)(hin + tb*1024 + col);
                    float2 oa, ob;
                    oa.x = fmaf(sigm(dg.x), du.x, ha.x);
                    oa.y = fmaf(sigm(dg.y), du.y, ha.y);
                    ob.x = fmaf(sigm(dg.z), du.z, hb.x);
                    ob.y = fmaf(sigm(dg.w), du.w, hb.y);
                    *(float2*)(hout + ta*1024 + col) = oa;
                    *(float2*)(hout + tb*1024 + col) = ob;
                    accg[m*4 + n] = make_float4(0.f,0.f,0.f,0.f);
                    accu[m*4 + n] = make_float4(0.f,0.f,0.f,0.f);
                }
        }
    }
}

// ---------------- fused ff GEMM: silu(g)*f -> g_ff ----------------
__global__ __launch_bounds__(256)
void ff_k(const __half* __restrict__ z, const __half* __restrict__ P,
          const __half* __restrict__ Wg, const __half* __restrict__ Wf,
          const __half* __restrict__ Ag, const __half* __restrict__ Af){
    extern __shared__ float sm[];
    uint32_t sb = smem_u32(sm);
    float* park = sm + 116736/4;
    int tid = threadIdx.x, warp = tid >> 5, lane = tid & 31;
    int wm = warp >> 1, wn = warp & 1;
    int tile = blockIdx.x, nblk = blockIdx.y, nsub = blockIdx.z;
    int n0 = nblk*352 + nsub*176;
    size_t tok0 = (size_t)tile*128;

    float4 acc[22];
    #pragma unroll
    for (int i = 0; i < 22; i++) acc[i] = make_float4(0.f,0.f,0.f,0.f);

    auto fill = [&](int q, int buf){
        uint32_t aB = sb + (uint32_t)buf*38912u;
        uint32_t bB = aB + 16384u;
        int ph = (q >= 3), s = ph ? (q - 3) : q;
        const __half* W = ph ? Wf : Wg;
        if (s < 2){
            stage_tile<1024>(aB, z + tok0*1024 + nblk*128 + (s << 6), 1024);
            stage_tile<1408>(bB, W + (size_t)n0*128 + (s << 6), 128);
        } else {
            stage_tile<1024>(aB, P + tok0*64, 64);
            const __half* Alr = ph ? Af : Ag;
            #pragma unroll
            for (int i = 0; i < 6; i++){
                int idx = tid + i*256;
                if (idx >= 1408) continue;
                int r = idx >> 3, c4 = idx & 7;
                uint32_t so = bB + r*128 + ((uint32_t)(c4 ^ (r & 7)) << 4);
                int lo = (c4 < 4);
                int use = ph ? !lo : lo;
                int cc = ph ? (c4 - 4) : c4;
                cp16(so, Alr + (size_t)(n0 + r)*32 + ((use ? cc : 0) << 3), use ? 16 : 0);
            }
        }
    };

    fill(0, 0); CPCOMMIT();
    fill(1, 1); CPCOMMIT();
    for (int q = 0; q < 6; q++){
        asm volatile("cp.async.wait_group 1;" ::: "memory");
        __syncthreads();
        uint32_t aB = sb + (uint32_t)(q % 3)*38912u;
        compLh<2,11>(aB, aB + 16384u, acc, wm*32, wn*88, lane);
        if (q == 2){
            float4* pk = (float4*)park + (size_t)tid*22;
            #pragma unroll
            for (int i = 0; i < 22; i++){
                pk[i] = acc[i];
                acc[i] = make_float4(0.f,0.f,0.f,0.f);
            }
        }
        if (q + 2 < 6) fill(q + 2, (q + 2) % 3);
        CPCOMMIT();
    }

    const float4* pk = (const float4*)park + (size_t)tid*22;
    int lr = lane >> 2, lc2 = (lane & 3)*2;
    #pragma unroll
    for (int m = 0; m < 2; m++)
        #pragma unroll
        for (int n = 0; n < 11; n++){
            int r0 = wm*32 + m*16 + lr;
            int col = n0 + wn*88 + n*8 + lc2;
            float4 f = acc[m*11 + n];
            float4 g = pk[m*11 + n];
            size_t ia = (tok0 + r0)*2816 + col;
            size_t ib = (tok0 + r0 + 8)*2816 + col;
            *(__half2*)(g_ff + ia) = __floats2half2_rn(g.x*sigm(g.x)*f.x, g.y*sigm(g.y)*f.y);
            *(__half2*)(g_ff + ib) = __floats2half2_rn(g.z*sigm(g.z)*f.z, g.w*sigm(g.w)*f.w);
        }
}

// ---------------- Pp partials (2 tiles/CTA, B resident) ----------------
// grid (64, 8). B: 6 slabs x 4KB resident; A: 2 x 16KB stream.
__global__ __launch_bounds__(256, 3)
void pp_k(const __half* __restrict__ ffpB){
    extern __shared__ float sm[];
    uint32_t sb = smem_u32(sm);
    uint32_t SB = sb + 32768u;
    int tid = threadIdx.x, warp = tid >> 5, lane = tid & 31;
    int wm = warp >> 1, wn = warp & 1;
    int chunk = blockIdx.y;
    int tile0 = blockIdx.x*2;

    for (int s = 0; s < 6; s++){
        int vc = (s < 5) ? 8 : 4;
        for (int i = tid; i < 256; i += 256){
            int r = i >> 3, c4 = i & 7;
            int ok = (c4 < vc);
            cp16(SB + s*4096u + r*128 + ((uint32_t)(c4 ^ (r & 7)) << 4),
                 ffpB + (size_t)r*2816 + chunk*352 + (s << 6) + ((ok ? c4 : 0) << 3), ok ? 16 : 0);
        }
    }
    auto fillA = [&](int q){
        int t = q/6, s = q - t*6;
        int vc = (s < 5) ? 8 : 4;
        size_t tok0 = (size_t)(tile0 + t)*128;
        stage_tile_vc<1024>(sb + (uint32_t)(q & 1)*16384u,
                            g_ff + tok0*2816 + chunk*352 + (s << 6), 2816, vc);
    };
    fillA(0); CPCOMMIT();

    float4 acc[4];
    #pragma unroll
    for (int i = 0; i < 4; i++) acc[i] = make_float4(0.f,0.f,0.f,0.f);

    int lr = lane >> 2, lc2 = (lane & 3)*2;
    for (int q = 0; q < 12; q++){
        CPWAIT0(); __syncthreads();
        if (q + 1 < 12){ fillA(q + 1); CPCOMMIT(); }
        int t = q/6, s = q - t*6;
        compLh<2,2>(sb + (uint32_t)(q & 1)*16384u, SB + s*4096u, acc, wm*32, wn*16, lane);
        if (s == 5){
            size_t tok0 = (size_t)(tile0 + t)*128;
            float* dst = g_part + (size_t)chunk*524288u;
            #pragma unroll
            for (int m = 0; m < 2; m++)
                #pragma unroll
                for (int n = 0; n < 2; n++){
                    int r0 = wm*32 + m*16 + lr;
                    int col = wn*16 + n*8 + lc2;
                    float4 d = acc[m*2 + n];
                    *(float2*)(dst + (tok0 + r0    )*32 + col) = make_float2(d.x, d.y);
                    *(float2*)(dst + (tok0 + r0 + 8)*32 + col) = make_float2(d.z, d.w);
                    acc[m*2 + n] = make_float4(0.f,0.f,0.f,0.f);
                }
        }
    }
}

// ---------------- out = h + ffp(ff) (2 tiles/CTA, weights resident) ----------------
// grid (64, 16). B: 7 slabs x 8KB resident; A: 2 x 16KB stream.
__global__ __launch_bounds__(256, 2)
void out_k(const float* __restrict__ hin, float* __restrict__ out,
           const __half* __restrict__ Wp, const __half* __restrict__ Ap){
    extern __shared__ float sm[];
    uint32_t sb = smem_u32(sm);
    uint32_t SB = sb + 32768u;
    int tid = threadIdx.x, warp = tid >> 5, lane = tid & 31;
    int wm = warp >> 1, wn = warp & 1;
    int nb2 = blockIdx.y;
    int nblk = nb2 >> 1, nh = nb2 & 1;
    int wrow0 = nblk*128 + nh*64;
    int tile0 = blockIdx.x*2;

    for (int s = 0; s < 6; s++){
        int vc = (s < 5) ? 8 : 4;
        for (int i = tid; i < 512; i += 256){
            int r = i >> 3, c4 = i & 7;
            int ok = (c4 < vc);
            cp16(SB + s*8192u + r*128 + ((uint32_t)(c4 ^ (r & 7)) << 4),
                 Wp + (size_t)(wrow0 + r)*352 + (s << 6) + ((ok ? c4 : 0) << 3), ok ? 16 : 0);
        }
    }
    for (int i = tid; i < 512; i += 256){
        int r = i >> 3, c4 = i & 7;
        int ok = (c4 < 4);
        cp16(SB + 49152u + r*128 + ((uint32_t)(c4 ^ (r & 7)) << 4),
             Ap + (size_t)(wrow0 + r)*32 + ((ok ? c4 : 0) << 3), ok ? 16 : 0);
    }
    auto fillA = [&](int q){
        int t = q/7, s = q - t*7;
        size_t tok0 = (size_t)(tile0 + t)*128;
        uint32_t aB = sb + (uint32_t)(q & 1)*16384u;
        if (s < 6){
            int vc = (s < 5) ? 8 : 4;
            stage_tile_vc<1024>(aB, g_ff + tok0*2816 + nblk*352 + (s << 6), 2816, vc);
        } else {
            stage_tile_vc<1024>(aB, g_Pp + tok0*32, 32, 4);
        }
    };
    fillA(0); CPCOMMIT();

    float4 acc[8];
    #pragma unroll
    for (int i = 0; i < 8; i++) acc[i] = make_float4(0.f,0.f,0.f,0.f);

    int lr = lane >> 2, lc2 = (lane & 3)*2;
    for (int q = 0; q < 14; q++){
        CPWAIT0(); __syncthreads();
        if (q + 1 < 14){ fillA(q + 1); CPCOMMIT(); }
        int t = q/7, s = q - t*7;
        compLh<2,4>(sb + (uint32_t)(q & 1)*16384u, SB + s*8192u, acc, wm*32, wn*32, lane);
        if (s == 6){
            size_t tok0 = (size_t)(tile0 + t)*128;
            #pragma unroll
            for (int m = 0; m < 2; m++)
                #pragma unroll
                for (int n = 0; n < 4; n++){
                    int r0 = wm*32 + m*16 + lr;
                    int col = wrow0 + wn*32 + n*8 + lc2;
                    float4 d = acc[m*4 + n];
                    size_t ta = tok0 + r0, tb = ta + 8;
                    float2 ha = *(const float2*)(hin + ta*1024 + col);
                    float2 hb = *(const float2*)(hin + tb*1024 + col);
                    *(float2*)(out + ta*1024 + col) = make_float2(ha.x + d.x, ha.y + d.y);
                    *(float2*)(out + tb*1024 + col) = make_float2(hb.x + d.z, hb.y + d.w);
                    acc[m*4 + n] = make_float4(0.f,0.f,0.f,0.f);
                }
        }
    }
}

// ---------------- launcher ----------------
template <typename T>
static void* symaddr(const T& s){
    void* p = nullptr;
    cudaGetSymbolAddress(&p, s);
    return p;
}

extern "C" void kernel_launch(void* const* d_in, const int* in_sizes, int n_in,
                              void* d_out, int out_size) {
    const float* x     = (const float*)d_in[0];
    const float* fg_W  = (const float*)d_in[1];
    const float* fg_A  = (const float*)d_in[2];
    const float* fg_B  = (const float*)d_in[3];
    const float* gu_W  = (const float*)d_in[4];
    const float* gu_A  = (const float*)d_in[5];
    const float* gu_B  = (const float*)d_in[6];
    const float* ffg_W = (const float*)d_in[7];
    const float* ffg_A = (const float*)d_in[8];
    const float* ffg_B = (const float*)d_in[9];
    const float* fff_W = (const float*)d_in[10];
    const float* fff_A = (const float*)d_in[11];
    const float* fff_B = (const float*)d_in[12];
    const float* ffp_W = (const float*)d_in[13];
    const float* ffp_A = (const float*)d_in[14];
    const float* ffp_B = (const float*)d_in[15];
    float* out = (float*)d_out;

    __half* z    = (__half*)symaddr(g_z);
    float*  h0   = (float*)symaddr(g_h0);
    float*  h1   = (float*)symaddr(g_h1);
    __half* P    = (__half*)symaddr(g_P);
    __half* Pp   = (__half*)symaddr(g_Pp);
    float*  part = (float*)symaddr(g_part);
    __half* wh   = (__half*)symaddr(g_wh);

    const int SM_P    = 32768 + 32768;          // 64 KB
    const int SM_MAIN = 32768 + 81920;          // 112 KB
    const int SM_FF   = 3*38912 + 90112;        // ~202 KB
    const int SM_PP   = 32768 + 24576;          // 56 KB
    const int SM_OUT  = 32768 + 57344;          // 88 KB
    cudaFuncSetAttribute(p_k,    cudaFuncAttributeMaxDynamicSharedMemorySize, SM_P);
    cudaFuncSetAttribute(main_k, cudaFuncAttributeMaxDynamicSharedMemorySize, SM_MAIN);
    cudaFuncSetAttribute(ff_k,   cudaFuncAttributeMaxDynamicSharedMemorySize, SM_FF);
    cudaFuncSetAttribute(pp_k,   cudaFuncAttributeMaxDynamicSharedMemorySize, SM_PP);
    cudaFuncSetAttribute(out_k,  cudaFuncAttributeMaxDynamicSharedMemorySize, SM_OUT);

    cvt_k<<<dim3(352, 15), 256>>>(fg_W, gu_W, fg_A, gu_A, fg_B, gu_B,
                                  ffg_W, ffg_A, ffg_B, fff_W, fff_A, fff_B,
                                  ffp_W, ffp_A, ffp_B);

    const float* hcur = x;
    float* bufs[2] = {h0, h1};
    for (int it = 0; it < 4; it++){
        float* hnext = bufs[it & 1];
        rms_k<<<2048, 256>>>(hcur, z);
        p_k<<<dim3(64, 8), 256, SM_P>>>(z, wh + W_FGB, wh + W_GUB, 2, 2048, 2);
        pred_k<<<1024, 256>>>(P, part, 8, (size_t)1048576, 262144);
        main_k<<<dim3(64, 16), 256, SM_MAIN>>>(z, P, hcur, hnext,
                                               wh + W_FGW, wh + W_GUW,
                                               wh + W_FGA, wh + W_GUA);
        hcur = hnext;
    }
    rms_k<<<2048, 256>>>(hcur, z);
    p_k<<<dim3(64, 4), 256, SM_P>>>(z, wh + W_FFGB, wh + W_FFFB, 1, 1024, 2);
    pred_k<<<1024, 256>>>(P, part, 4, (size_t)1048576, 262144);
    ff_k<<<dim3(128, 8, 2), 256, SM_FF>>>(z, P, wh + W_FFGW, wh + W_FFFW,
                                          wh + W_FFGA, wh + W_FFFA);
    pp_k<<<dim3(64, 8), 256, SM_PP>>>(wh + W_FFPB);
    pred_k<<<512, 256>>>(Pp, part, 8, (size_t)524288, 131072);
    out_k<<<dim3(64, 16), 256, SM_OUT>>>(hcur, out, wh + W_FFPW, wh + W_FFPA);
}

// round 13
// speedup vs baseline: 1.5293x; 1.5293x over previous
#include <cuda_runtime.h>
#include <cuda_fp16.h>
#include <cstdint>
#include <cstddef>

#define EPSRMS 1.1920929e-07f

// ---------------- persistent device scratch ----------------
__device__ __half g_z [16777216];          // rmsnorm output (fp16)
__device__ float  g_h0[16777216];
__device__ float  g_h1[16777216];
__device__ __half g_P [16384*64];
__device__ __half g_Pp[16384*32];
__device__ __half g_ff[16384*2816];        // silu(ffg)*fff (fp16)
__device__ float  g_part[8*16384*64];
__device__ __half g_wh[2170880];           // fp16 weight copies

// weight offsets inside g_wh (element counts)
#define W_FGW  0
#define W_GUW  262144
#define W_FGA  524288
#define W_GUA  557056
#define W_FGB  589824
#define W_GUB  655360
#define W_FFGW 720896
#define W_FFGA 1081344
#define W_FFGB 1171456
#define W_FFFW 1204224
#define W_FFFA 1564672
#define W_FFFB 1654784
#define W_FFPW 1687552
#define W_FFPA 2048000
#define W_FFPB 2080768

// ---------------- helpers ----------------
__device__ __forceinline__ float sigm(float x){ return 1.0f/(1.0f+__expf(-x)); }

__device__ __forceinline__ uint32_t smem_u32(const void* p){
    uint32_t a;
    asm("{ .reg .u64 t; cvta.to.shared.u64 t, %1; cvt.u32.u64 %0, t; }" : "=r"(a) : "l"(p));
    return a;
}

__device__ __forceinline__ void mma16(float4& d, uint4 a, uint2 b){
    asm volatile(
        "mma.sync.aligned.m16n8k16.row.col.f32.f16.f16.f32 "
        "{%0,%1,%2,%3},{%4,%5,%6,%7},{%8,%9},{%0,%1,%2,%3};"
        : "+f"(d.x), "+f"(d.y), "+f"(d.z), "+f"(d.w)
        : "r"(a.x), "r"(a.y), "r"(a.z), "r"(a.w), "r"(b.x), "r"(b.y));
}

__device__ __forceinline__ void ldsm_x4(uint4& r, uint32_t a){
    asm volatile("ldmatrix.sync.aligned.m8n8.x4.shared.b16 {%0,%1,%2,%3}, [%4];"
                 : "=r"(r.x), "=r"(r.y), "=r"(r.z), "=r"(r.w) : "r"(a));
}
__device__ __forceinline__ void ldsm_x2(uint2& r, uint32_t a){
    asm volatile("ldmatrix.sync.aligned.m8n8.x2.shared.b16 {%0,%1}, [%2];"
                 : "=r"(r.x), "=r"(r.y) : "r"(a));
}

__device__ __forceinline__ void cp16(uint32_t dst, const void* src, int sz){
    asm volatile("cp.async.ca.shared.global [%0], [%1], 16, %2;"
                 :: "r"(dst), "l"(src), "r"(sz) : "memory");
}
#define CPCOMMIT() asm volatile("cp.async.commit_group;" ::: "memory")
#define CPWAITG1() asm volatile("cp.async.wait_group 1;"  ::: "memory")

// ---------------- smem staging (rows of 128B = 64 fp16, XOR-swizzled 16B chunks) ----------
template<int NCHUNK>   // NCHUNK = rows*8
__device__ __forceinline__ void stage_tile(uint32_t sb, const __half* src, size_t ld){
    int tid = threadIdx.x;
    #pragma unroll
    for (int i = 0; i < (NCHUNK + 255)/256; i++){
        int idx = tid + i*256;
        if ((NCHUNK & 255) && idx >= NCHUNK) continue;
        int r = idx >> 3, c4 = idx & 7;
        cp16(sb + r*128 + ((uint32_t)(c4 ^ (r & 7)) << 4),
             src + (size_t)r*ld + (c4 << 3), 16);
    }
}

template<int NCHUNK>
__device__ __forceinline__ void stage_tile_vc(uint32_t sb, const __half* src, size_t ld, int vc){
    int tid = threadIdx.x;
    #pragma unroll
    for (int i = 0; i < (NCHUNK + 255)/256; i++){
        int idx = tid + i*256;
        if ((NCHUNK & 255) && idx >= NCHUNK) continue;
        int r = idx >> 3, c4 = idx & 7;
        int ok = (c4 < vc);
        cp16(sb + r*128 + ((uint32_t)(c4 ^ (r & 7)) << 4),
             src + (size_t)r*ld + ((ok ? c4 : 0) << 3), ok ? 16 : 0);
    }
}

// A slab from token rows of z (fp16), causal shift (token = seq0+r-shift; zeros if <0)
__device__ __forceinline__ void stage_tok(uint32_t sb, const __half* zb,
                                          int seq0, int shift, int col){
    int tid = threadIdx.x;
    #pragma unroll
    for (int i = 0; i < 4; i++){
        int idx = tid + i*256;
        int r = idx >> 3, c4 = idx & 7;
        int s = seq0 + r - shift;
        int sz = (s >= 0) ? 16 : 0;
        if (s < 0) s = 0;
        cp16(sb + r*128 + ((uint32_t)(c4 ^ (r & 7)) << 4),
             zb + (size_t)s*1024 + col + (c4 << 3), sz);
    }
}

// ---------------- fp16 ldmatrix fragment compute over one K=64 slab ----------------
template<int MT, int NT>
__device__ __forceinline__ void compLh(uint32_t sAu, uint32_t sBu, float4* acc,
                                       int mb0, int nb0, int lane){
    const int arow = (lane & 7) + ((lane >> 3) & 1)*8;
    const int khA  = (lane >> 4) & 1;
    uint32_t aB[MT]; int asw[MT];
    #pragma unroll
    for (int m = 0; m < MT; m++){
        int r = mb0 + m*16 + arow;
        aB[m] = sAu + r*128; asw[m] = r & 7;
    }
    constexpr int NP = NT >> 1;
    const int brow = ((lane >> 4) & 1)*8 + (lane & 7);
    const int khB  = (lane >> 3) & 1;
    uint32_t bB[NP > 0 ? NP : 1]; int bsw[NP > 0 ? NP : 1];
    #pragma unroll
    for (int p = 0; p < NP; p++){
        int r = nb0 + p*16 + brow;
        bB[p] = sBu + r*128; bsw[p] = r & 7;
    }
    uint32_t oB = 0; int osw = 0;
    if constexpr (NT & 1){
        int r = nb0 + (NT-1)*8 + (lane & 7);
        oB = sBu + r*128; osw = r & 7;
    }
    const int khO = (lane >> 3) & 1;
    #pragma unroll
    for (int kc = 0; kc < 4; kc++){
        uint4 a[MT];
        #pragma unroll
        for (int m = 0; m < MT; m++)
            ldsm_x4(a[m], aB[m] + (uint32_t)((((kc<<1)|khA) ^ asw[m]) << 4));
        #pragma unroll
        for (int p = 0; p < NP; p++){
            uint4 b;
            ldsm_x4(b, bB[p] + (uint32_t)((((kc<<1)|khB) ^ bsw[p]) << 4));
            #pragma unroll
            for (int m = 0; m < MT; m++){
                mma16(acc[m*NT + 2*p    ], a[m], make_uint2(b.x, b.y));
                mma16(acc[m*NT + 2*p + 1], a[m], make_uint2(b.z, b.w));
            }
        }
        if constexpr (NT & 1){
            uint2 b;
            ldsm_x2(b, oB + (uint32_t)((((kc<<1)|khO) ^ osw) << 4));
            #pragma unroll
            for (int m = 0; m < MT; m++)
                mma16(acc[m*NT + NT - 1], a[m], b);
        }
    }
}

template<int MT, int NT>
__device__ __forceinline__ void compL2h(uint32_t sAu, uint32_t sB1, uint32_t sB2,
                                        float4* acc1, float4* acc2,
                                        int mb0, int nb0, int lane){
    static_assert((NT & 1) == 0, "NT even");
    const int arow = (lane & 7) + ((lane >> 3) & 1)*8;
    const int khA  = (lane >> 4) & 1;
    uint32_t aB[MT]; int asw[MT];
    #pragma unroll
    for (int m = 0; m < MT; m++){
        int r = mb0 + m*16 + arow;
        aB[m] = sAu + r*128; asw[m] = r & 7;
    }
    constexpr int NP = NT >> 1;
    const int brow = ((lane >> 4) & 1)*8 + (lane & 7);
    const int khB  = (lane >> 3) & 1;
    uint32_t b1B[NP], b2B[NP]; int bsw[NP];
    #pragma unroll
    for (int p = 0; p < NP; p++){
        int r = nb0 + p*16 + brow;
        b1B[p] = sB1 + r*128; b2B[p] = sB2 + r*128; bsw[p] = r & 7;
    }
    #pragma unroll
    for (int kc = 0; kc < 4; kc++){
        uint4 a[MT];
        #pragma unroll
        for (int m = 0; m < MT; m++)
            ldsm_x4(a[m], aB[m] + (uint32_t)((((kc<<1)|khA) ^ asw[m]) << 4));
        #pragma unroll
        for (int p = 0; p < NP; p++){
            uint32_t off = (uint32_t)((((kc<<1)|khB) ^ bsw[p]) << 4);
            uint4 b1, b2;
            ldsm_x4(b1, b1B[p] + off);
            ldsm_x4(b2, b2B[p] + off);
            #pragma unroll
            for (int m = 0; m < MT; m++){
                mma16(acc1[m*NT + 2*p    ], a[m], make_uint2(b1.x, b1.y));
                mma16(acc1[m*NT + 2*p + 1], a[m], make_uint2(b1.z, b1.w));
                mma16(acc2[m*NT + 2*p    ], a[m], make_uint2(b2.x, b2.y));
                mma16(acc2[m*NT + 2*p + 1], a[m], make_uint2(b2.z, b2.w));
            }
        }
    }
}

// ---------------- weight fp16 conversion ----------------
__global__ void cvt_k(const float* p0, const float* p1, const float* p2, const float* p3,
                      const float* p4, const float* p5, const float* p6, const float* p7,
                      const float* p8, const float* p9, const float* p10, const float* p11,
                      const float* p12, const float* p13, const float* p14){
    const float* srcs[15] = {p0,p1,p2,p3,p4,p5,p6,p7,p8,p9,p10,p11,p12,p13,p14};
    const int sz4[15] = {65536,65536,8192,8192,16384,16384,90112,22528,8192,
                         90112,22528,8192,90112,8192,22528};
    const int off[15] = {W_FGW,W_GUW,W_FGA,W_GUA,W_FGB,W_GUB,W_FFGW,W_FFGA,W_FFGB,
                         W_FFFW,W_FFFA,W_FFFB,W_FFPW,W_FFPA,W_FFPB};
    int t = blockIdx.y;
    int i = blockIdx.x*256 + threadIdx.x;
    if (i >= sz4[t]) return;
    float4 v = ((const float4*)srcs[t])[i];
    __half2* dst = (__half2*)(g_wh + off[t]);
    dst[2*i]     = __floats2half2_rn(v.x, v.y);
    dst[2*i + 1] = __floats2half2_rn(v.z, v.w);
}

// ---------------- rmsnorm: h -> z (fp16 output) ----------------
__global__ __launch_bounds__(256)
void rms_k(const float* __restrict__ h, __half* __restrict__ z){
    int warp = threadIdx.x >> 5, lane = threadIdx.x & 31;
    size_t tok = (size_t)blockIdx.x*8 + warp;
    const float4* hr = (const float4*)(h + tok*1024);
    float4 v[8]; float ss = 0.f;
    #pragma unroll
    for (int j = 0; j < 8; j++){
        v[j] = hr[lane + 32*j];
        ss += v[j].x*v[j].x + v[j].y*v[j].y + v[j].z*v[j].z + v[j].w*v[j].w;
    }
    #pragma unroll
    for (int o = 16; o; o >>= 1) ss += __shfl_xor_sync(0xffffffffu, ss, o);
    float sc = rsqrtf(ss*(1.f/1024.f) + EPSRMS);
    __half2* zr = (__half2*)(z + tok*1024);
    #pragma unroll
    for (int j = 0; j < 8; j++){
        int p = lane + 32*j;
        zr[2*p]     = __floats2half2_rn(v[j].x*sc, v[j].y*sc);
        zr[2*p + 1] = __floats2half2_rn(v[j].z*sc, v[j].w*sc);
    }
}

// ---------------- low-rank projection, column-split: P written directly ----------------
// grid (128 tiles, 4 colgroups). Each CTA: full K for 16 P-columns.
// Slab q: half = q>>4 (0: z_t cols, 1: z_{t-1}), col = (q&15)*64.
__global__ __launch_bounds__(256, 4)
void p_k(const __half* __restrict__ z, __half* __restrict__ P,
         const __half* __restrict__ B1, const __half* __restrict__ B2,
         int halves, int ldB){
    extern __shared__ float sm[];
    uint32_t sb = smem_u32(sm);
    int tid = threadIdx.x, warp = tid >> 5, lane = tid & 31;
    int tile = blockIdx.x, cg = blockIdx.y;
    int batch = tile >> 4, seq0 = (tile & 15) << 7;
    const __half* zb = z + (size_t)batch*2048*1024;
    int Q = halves << 4;

    auto fill = [&](int q, int buf){
        uint32_t aB = sb + (uint32_t)buf*18432u;
        uint32_t bB = aB + 16384u;
        int half = q >> 4, col = (q & 15) << 6;
        stage_tok(aB, zb, seq0, half, col);
        if (tid < 128){
            int r = tid >> 3, c4 = tid & 7;
            int gr = cg*16 + r;
            const __half* src = ((gr < 32) ? B1 : B2)
                              + (size_t)(gr & 31)*ldB + half*1024 + col + (c4 << 3);
            cp16(bB + r*128 + ((uint32_t)(c4 ^ (r & 7)) << 4), src, 16);
        }
    };
    fill(0, 0); CPCOMMIT();
    fill(1, 1); CPCOMMIT();

    float4 acc[2];
    acc[0] = make_float4(0.f,0.f,0.f,0.f);
    acc[1] = make_float4(0.f,0.f,0.f,0.f);
    for (int q = 0; q < Q; q++){
        CPWAITG1(); __syncthreads();
        uint32_t aB = sb + (uint32_t)(q % 3)*18432u;
        compLh<1,2>(aB, aB + 16384u, acc, warp*16, 0, lane);
        if (q + 2 < Q) fill(q + 2, (q + 2) % 3);
        CPCOMMIT();
    }

    int lr = lane >> 2, lc2 = (lane & 3)*2;
    size_t tok0 = (size_t)tile*128;
    #pragma unroll
    for (int n = 0; n < 2; n++){
        int r0 = warp*16 + lr;
        int col = cg*16 + n*8 + lc2;
        float4 d = acc[n];
        *(__half2*)(P + (tok0 + r0    )*64 + col) = __floats2half2_rn(d.x, d.y);
        *(__half2*)(P + (tok0 + r0 + 8)*64 + col) = __floats2half2_rn(d.z, d.w);
    }
}

// reduce partials -> fp16 (used only for Pp)
__global__ void pred_k(__half* __restrict__ dst, const float* __restrict__ src,
                       int nch, size_t cstride, int n4){
    int i = blockIdx.x*256 + threadIdx.x;
    if (i >= n4) return;
    float4 a = ((const float4*)src)[i];
    for (int c = 1; c < nch; c++){
        float4 v = ((const float4*)(src + (size_t)c*cstride))[i];
        a.x += v.x; a.y += v.y; a.z += v.z; a.w += v.w;
    }
    __half2* d2 = (__half2*)dst;
    d2[2*i]     = __floats2half2_rn(a.x, a.y);
    d2[2*i + 1] = __floats2half2_rn(a.z, a.w);
}

// ---------------- iteration main GEMM (4 weight slabs + 1 shared lowrank slab) ----------
__global__ __launch_bounds__(256)
void main_k(const __half* __restrict__ z, const __half* __restrict__ P,
            const float* __restrict__ hin, float* __restrict__ hout,
            const __half* __restrict__ Wg, const __half* __restrict__ Wu,
            const __half* __restrict__ Ag, const __half* __restrict__ Au){
    extern __shared__ float sm[];
    uint32_t sb = smem_u32(sm);
    int tid = threadIdx.x, warp = tid >> 5, lane = tid & 31;
    int wm = warp >> 1, wn = warp & 1;
    int tile = blockIdx.x, nb2 = blockIdx.y;
    int nblk = nb2 >> 1, nh = nb2 & 1;
    int batch = tile >> 4, seq0 = (tile & 15) << 7;
    const __half* zb = z + (size_t)batch*2048*1024;
    int shift = (nblk >= 4) ? 1 : 0;
    int colbase0 = (nblk & 3) << 8;
    size_t tok0 = (size_t)tile*128;
    int wrow0 = nblk*128 + nh*64;

    float4 accg[8], accu[8];
    #pragma unroll
    for (int i = 0; i < 8; i++){
        accg[i] = make_float4(0.f,0.f,0.f,0.f);
        accu[i] = make_float4(0.f,0.f,0.f,0.f);
    }

    auto fill = [&](int s, int buf){
        uint32_t aB = sb + (uint32_t)buf*32768u;
        uint32_t gB = aB + 16384u, uB = aB + 24576u;
        if (s < 4){
            stage_tok(aB, zb, seq0, shift, colbase0 + (s << 6));
            const __half* g = Wg + (size_t)wrow0*256 + (s << 6);
            const __half* u = Wu + (size_t)wrow0*256 + (s << 6);
            #pragma unroll
            for (int i = 0; i < 2; i++){
                int idx = tid + i*256;
                int r = idx >> 3, c4 = idx & 7;
                uint32_t so = r*128 + ((uint32_t)(c4 ^ (r & 7)) << 4);
                cp16(gB + so, g + (size_t)r*256 + (c4 << 3), 16);
                cp16(uB + so, u + (size_t)r*256 + (c4 << 3), 16);
            }
        } else {
            // shared lowrank slab: A = P[:,0:64]; Bg = [Ag|0], Bu = [0|Au]
            stage_tile<1024>(aB, P + tok0*64, 64);
            #pragma unroll
            for (int i = 0; i < 2; i++){
                int idx = tid + i*256;
                int r = idx >> 3, c4 = idx & 7;
                uint32_t so = r*128 + ((uint32_t)(c4 ^ (r & 7)) << 4);
                int glo = (c4 < 4);
                cp16(gB + so, Ag + (size_t)(wrow0 + r)*32 + ((glo ? c4 : 0) << 3), glo ? 16 : 0);
                cp16(uB + so, Au + (size_t)(wrow0 + r)*32 + ((glo ? 0 : (c4 - 4)) << 3), glo ? 0 : 16);
            }
        }
    };

    fill(0, 0); CPCOMMIT();
    fill(1, 1); CPCOMMIT();
    for (int s = 0; s < 5; s++){
        CPWAITG1(); __syncthreads();
        uint32_t aB = sb + (uint32_t)(s % 3)*32768u;
        compL2h<2,4>(aB, aB + 16384u, aB + 24576u, accg, accu, wm*32, wn*32, lane);
        if (s + 2 < 5) fill(s + 2, (s + 2) % 3);
        CPCOMMIT();
    }

    int lr = lane >> 2, lc2 = (lane & 3)*2;
    #pragma unroll
    for (int m = 0; m < 2; m++)
        #pragma unroll
        for (int n = 0; n < 4; n++){
            int r0 = wm*32 + m*16 + lr;
            int col = wrow0 + wn*32 + n*8 + lc2;
            float4 dg = accg[m*4 + n], du = accu[m*4 + n];
            size_t ta = tok0 + r0, tb = ta + 8;
            float2 ha = *(const float2*)(hin + ta*1024 + col);
            float2 hb = *(const float2*)(hin + tb*1024 + col);
            float2 oa, ob;
            oa.x = fmaf(sigm(dg.x), du.x, ha.x);
            oa.y = fmaf(sigm(dg.y), du.y, ha.y);
            ob.x = fmaf(sigm(dg.z), du.z, hb.x);
            ob.y = fmaf(sigm(dg.w), du.w, hb.y);
            *(float2*)(hout + ta*1024 + col) = oa;
            *(float2*)(hout + tb*1024 + col) = ob;
        }
}

// ---------------- fused ff GEMM: g phase -> park, f phase -> silu(g)*f -> g_ff ------------
__global__ __launch_bounds__(256)
void ff_k(const __half* __restrict__ z, const __half* __restrict__ P,
          const __half* __restrict__ Wg, const __half* __restrict__ Wf,
          const __half* __restrict__ Ag, const __half* __restrict__ Af){
    extern __shared__ float sm[];
    uint32_t sb = smem_u32(sm);
    float* park = sm + 116736/4;
    int tid = threadIdx.x, warp = tid >> 5, lane = tid & 31;
    int wm = warp >> 1, wn = warp & 1;
    int tile = blockIdx.x, nblk = blockIdx.y, nsub = blockIdx.z;
    int n0 = nblk*352 + nsub*176;
    size_t tok0 = (size_t)tile*128;

    float4 acc[22];
    #pragma unroll
    for (int i = 0; i < 22; i++) acc[i] = make_float4(0.f,0.f,0.f,0.f);

    auto fill = [&](int q, int buf){
        uint32_t aB = sb + (uint32_t)buf*38912u;
        uint32_t bB = aB + 16384u;
        int ph = (q >= 3), s = ph ? (q - 3) : q;
        const __half* W = ph ? Wf : Wg;
        if (s < 2){
            stage_tile<1024>(aB, z + tok0*1024 + nblk*128 + (s << 6), 1024);
            stage_tile<1408>(bB, W + (size_t)n0*128 + (s << 6), 128);
        } else {
            stage_tile<1024>(aB, P + tok0*64, 64);
            const __half* Alr = ph ? Af : Ag;
            #pragma unroll
            for (int i = 0; i < 6; i++){
                int idx = tid + i*256;
                if (idx >= 1408) continue;
                int r = idx >> 3, c4 = idx & 7;
                uint32_t so = bB + r*128 + ((uint32_t)(c4 ^ (r & 7)) << 4);
                int lo = (c4 < 4);
                int use = ph ? !lo : lo;             // g: chunks 0-3; f: chunks 4-7
                int cc = ph ? (c4 - 4) : c4;
                cp16(so, Alr + (size_t)(n0 + r)*32 + ((use ? cc : 0) << 3), use ? 16 : 0);
            }
        }
    };

    fill(0, 0); CPCOMMIT();
    fill(1, 1); CPCOMMIT();
    for (int q = 0; q < 6; q++){
        CPWAITG1();
        __syncthreads();
        uint32_t aB = sb + (uint32_t)(q % 3)*38912u;
        compLh<2,11>(aB, aB + 16384u, acc, wm*32, wn*88, lane);
        if (q == 2){
            float4* pk = (float4*)park + (size_t)tid*22;
            #pragma unroll
            for (int i = 0; i < 22; i++){
                pk[i] = acc[i];
                acc[i] = make_float4(0.f,0.f,0.f,0.f);
            }
        }
        if (q + 2 < 6) fill(q + 2, (q + 2) % 3);
        CPCOMMIT();
    }

    const float4* pk = (const float4*)park + (size_t)tid*22;
    int lr = lane >> 2, lc2 = (lane & 3)*2;
    #pragma unroll
    for (int m = 0; m < 2; m++)
        #pragma unroll
        for (int n = 0; n < 11; n++){
            int r0 = wm*32 + m*16 + lr;
            int col = n0 + wn*88 + n*8 + lc2;
            float4 f = acc[m*11 + n];
            float4 g = pk[m*11 + n];
            size_t ia = (tok0 + r0)*2816 + col;
            size_t ib = (tok0 + r0 + 8)*2816 + col;
            *(__half2*)(g_ff + ia) = __floats2half2_rn(g.x*sigm(g.x)*f.x, g.y*sigm(g.y)*f.y);
            *(__half2*)(g_ff + ib) = __floats2half2_rn(g.z*sigm(g.z)*f.z, g.w*sigm(g.w)*f.w);
        }
}

// ---------------- Pp partials: ff . ffp_B^T, K-split 8 x 352 (6 slabs, tail zfill) --------
__global__ __launch_bounds__(256)
void pp_k(const __half* __restrict__ ffpB){
    extern __shared__ float sm[];
    uint32_t sb = smem_u32(sm);
    int tid = threadIdx.x, warp = tid >> 5, lane = tid & 31;
    int wm = warp >> 1, wn = warp & 1;
    int tile = blockIdx.x, chunk = blockIdx.y;
    size_t tok0 = (size_t)tile*128;

    float4 acc[4];
    #pragma unroll
    for (int i = 0; i < 4; i++) acc[i] = make_float4(0.f,0.f,0.f,0.f);

    auto fill = [&](int s, int buf){
        uint32_t aB = sb + (uint32_t)buf*20480u;
        uint32_t bB = aB + 16384u;
        int vc = (s < 5) ? 8 : 4;                    // tail slab: 32 valid cols
        stage_tile_vc<1024>(aB, g_ff + tok0*2816 + chunk*352 + (s << 6), 2816, vc);
        stage_tile_vc<256>(bB, ffpB + chunk*352 + (s << 6), 2816, vc);
    };

    fill(0, 0); CPCOMMIT();
    fill(1, 1); CPCOMMIT();
    for (int s = 0; s < 6; s++){
        CPWAITG1(); __syncthreads();
        uint32_t aB = sb + (uint32_t)(s % 3)*20480u;
        compLh<2,2>(aB, aB + 16384u, acc, wm*32, wn*16, lane);
        if (s + 2 < 6) fill(s + 2, (s + 2) % 3);
        CPCOMMIT();
    }

    float* dst = g_part + (size_t)chunk*524288u;
    int lr = lane >> 2, lc2 = (lane & 3)*2;
    #pragma unroll
    for (int m = 0; m < 2; m++)
        #pragma unroll
        for (int n = 0; n < 2; n++){
            int r0 = wm*32 + m*16 + lr;
            int col = wn*16 + n*8 + lc2;
            float4 d = acc[m*2 + n];
            *(float2*)(dst + (tok0 + r0    )*32 + col) = make_float2(d.x, d.y);
            *(float2*)(dst + (tok0 + r0 + 8)*32 + col) = make_float2(d.z, d.w);
        }
}

// ---------------- out = h + ffp(ff) (5 full + tail + lowrank = 7 slabs) ----------------
__global__ __launch_bounds__(256)
void out_k(const float* __restrict__ hin, float* __restrict__ out,
           const __half* __restrict__ Wp, const __half* __restrict__ Ap){
    extern __shared__ float sm[];
    uint32_t sb = smem_u32(sm);
    int tid = threadIdx.x, warp = tid >> 5, lane = tid & 31;
    int wm = warp >> 1, wn = warp & 1;
    int tile = blockIdx.x, nb2 = blockIdx.y;
    int nblk = nb2 >> 1, nh = nb2 & 1;
    size_t tok0 = (size_t)tile*128;
    int wrow0 = nblk*128 + nh*64;

    float4 acc[8];
    #pragma unroll
    for (int i = 0; i < 8; i++) acc[i] = make_float4(0.f,0.f,0.f,0.f);

    auto fill = [&](int s, int buf){
        uint32_t aB = sb + (uint32_t)buf*24576u;
        uint32_t bB = aB + 16384u;
        if (s < 6){
            int vc = (s < 5) ? 8 : 4;
            stage_tile_vc<1024>(aB, g_ff + tok0*2816 + nblk*352 + (s << 6), 2816, vc);
            stage_tile_vc<512>(bB, Wp + (size_t)wrow0*352 + (s << 6), 352, vc);
        } else {
            stage_tile_vc<1024>(aB, g_Pp + tok0*32, 32, 4);
            stage_tile_vc<512>(bB, Ap + (size_t)wrow0*32, 32, 4);
        }
    };

    fill(0, 0); CPCOMMIT();
    fill(1, 1); CPCOMMIT();
    for (int s = 0; s < 7; s++){
        CPWAITG1(); __syncthreads();
        uint32_t aB = sb + (uint32_t)(s % 3)*24576u;
        compLh<2,4>(aB, aB + 16384u, acc, wm*32, wn*32, lane);
        if (s + 2 < 7) fill(s + 2, (s + 2) % 3);
        CPCOMMIT();
    }

    int lr = lane >> 2, lc2 = (lane & 3)*2;
    #pragma unroll
    for (int m = 0; m < 2; m++)
        #pragma unroll
        for (int n = 0; n < 4; n++){
            int r0 = wm*32 + m*16 + lr;
            int col = wrow0 + wn*32 + n*8 + lc2;
            float4 d = acc[m*4 + n];
            size_t ta = tok0 + r0, tb = ta + 8;
            float2 ha = *(const float2*)(hin + ta*1024 + col);
            float2 hb = *(const float2*)(hin + tb*1024 + col);
            *(float2*)(out + ta*1024 + col) = make_float2(ha.x + d.x, ha.y + d.y);
            *(float2*)(out + tb*1024 + col) = make_float2(hb.x + d.z, hb.y + d.w);
        }
}

// ---------------- launcher ----------------
template <typename T>
static void* symaddr(const T& s){
    void* p = nullptr;
    cudaGetSymbolAddress(&p, s);
    return p;
}

extern "C" void kernel_launch(void* const* d_in, const int* in_sizes, int n_in,
                              void* d_out, int out_size) {
    const float* x     = (const float*)d_in[0];
    const float* fg_W  = (const float*)d_in[1];
    const float* fg_A  = (const float*)d_in[2];
    const float* fg_B  = (const float*)d_in[3];
    const float* gu_W  = (const float*)d_in[4];
    const float* gu_A  = (const float*)d_in[5];
    const float* gu_B  = (const float*)d_in[6];
    const float* ffg_W = (const float*)d_in[7];
    const float* ffg_A = (const float*)d_in[8];
    const float* ffg_B = (const float*)d_in[9];
    const float* fff_W = (const float*)d_in[10];
    const float* fff_A = (const float*)d_in[11];
    const float* fff_B = (const float*)d_in[12];
    const float* ffp_W = (const float*)d_in[13];
    const float* ffp_A = (const float*)d_in[14];
    const float* ffp_B = (const float*)d_in[15];
    float* out = (float*)d_out;

    __half* z    = (__half*)symaddr(g_z);
    float*  h0   = (float*)symaddr(g_h0);
    float*  h1   = (float*)symaddr(g_h1);
    __half* P    = (__half*)symaddr(g_P);
    __half* Pp   = (__half*)symaddr(g_Pp);
    float*  part = (float*)symaddr(g_part);
    __half* wh   = (__half*)symaddr(g_wh);

    const int SM_P    = 3*18432;            // 54 KB
    const int SM_MAIN = 3*32768;            // 96 KB
    const int SM_FF   = 3*38912 + 90112;    // ~202 KB (3-stage + park)
    const int SM_PP   = 3*20480;            // 60 KB
    const int SM_OUT  = 3*24576;            // 72 KB
    cudaFuncSetAttribute(p_k,    cudaFuncAttributeMaxDynamicSharedMemorySize, SM_P);
    cudaFuncSetAttribute(main_k, cudaFuncAttributeMaxDynamicSharedMemorySize, SM_MAIN);
    cudaFuncSetAttribute(ff_k,   cudaFuncAttributeMaxDynamicSharedMemorySize, SM_FF);
    cudaFuncSetAttribute(pp_k,   cudaFuncAttributeMaxDynamicSharedMemorySize, SM_PP);
    cudaFuncSetAttribute(out_k,  cudaFuncAttributeMaxDynamicSharedMemorySize, SM_OUT);

    cvt_k<<<dim3(352, 15), 256>>>(fg_W, gu_W, fg_A, gu_A, fg_B, gu_B,
                                  ffg_W, ffg_A, ffg_B, fff_W, fff_A, fff_B,
                                  ffp_W, ffp_A, ffp_B);

    const float* hcur = x;
    float* bufs[2] = {h0, h1};
    for (int it = 0; it < 4; it++){
        float* hnext = bufs[it & 1];
        rms_k<<<2048, 256>>>(hcur, z);
        p_k<<<dim3(128, 4), 256, SM_P>>>(z, P, wh + W_FGB, wh + W_GUB, 2, 2048);
        main_k<<<dim3(128, 16), 256, SM_MAIN>>>(z, P, hcur, hnext,
                                                wh + W_FGW, wh + W_GUW,
                                                wh + W_FGA, wh + W_GUA);
        hcur = hnext;
    }
    rms_k<<<2048, 256>>>(hcur, z);
    p_k<<<dim3(128, 4), 256, SM_P>>>(z, P, wh + W_FFGB, wh + W_FFFB, 1, 1024);
    ff_k<<<dim3(128, 8, 2), 256, SM_FF>>>(z, P, wh + W_FFGW, wh + W_FFFW,
                                          wh + W_FFGA, wh + W_FFFA);
    pp_k<<<dim3(128, 8), 256, SM_PP>>>(wh + W_FFPB);
    pred_k<<<512, 256>>>(Pp, part, 8, (size_t)524288, 131072);
    out_k<<<dim3(128, 16), 256, SM_OUT>>>(hcur, out, wh + W_FFPW, wh + W_FFPA);
}

// round 15
// speedup vs baseline: 1.6822x; 1.1000x over previous
#include <cuda_runtime.h>
#include <cuda_fp16.h>
#include <cstdint>
#include <cstddef>

#define EPSRMS 1.1920929e-07f

// ---------------- persistent device scratch ----------------
__device__ __half g_z [16777216];          // rmsnorm output (fp16)
__device__ float  g_h0[16777216];
__device__ float  g_h1[16777216];
__device__ __half g_P [16384*64];
__device__ __half g_Pp[16384*32];
__device__ __half g_ff[16384*2816];        // silu(ffg)*fff (fp16)
__device__ float  g_part[8*16384*64];
__device__ __half g_wh[2170880];           // fp16 weight copies

// weight offsets inside g_wh (element counts)
#define W_FGW  0
#define W_GUW  262144
#define W_FGA  524288
#define W_GUA  557056
#define W_FGB  589824
#define W_GUB  655360
#define W_FFGW 720896
#define W_FFGA 1081344
#define W_FFGB 1171456
#define W_FFFW 1204224
#define W_FFFA 1564672
#define W_FFFB 1654784
#define W_FFPW 1687552
#define W_FFPA 2048000
#define W_FFPB 2080768

// ---------------- helpers ----------------
__device__ __forceinline__ float sigm(float x){ return 1.0f/(1.0f+__expf(-x)); }

__device__ __forceinline__ uint32_t smem_u32(const void* p){
    uint32_t a;
    asm("{ .reg .u64 t; cvta.to.shared.u64 t, %1; cvt.u32.u64 %0, t; }" : "=r"(a) : "l"(p));
    return a;
}

__device__ __forceinline__ void mma16(float4& d, uint4 a, uint2 b){
    asm volatile(
        "mma.sync.aligned.m16n8k16.row.col.f32.f16.f16.f32 "
        "{%0,%1,%2,%3},{%4,%5,%6,%7},{%8,%9},{%0,%1,%2,%3};"
        : "+f"(d.x), "+f"(d.y), "+f"(d.z), "+f"(d.w)
        : "r"(a.x), "r"(a.y), "r"(a.z), "r"(a.w), "r"(b.x), "r"(b.y));
}

__device__ __forceinline__ void ldsm_x4(uint4& r, uint32_t a){
    asm volatile("ldmatrix.sync.aligned.m8n8.x4.shared.b16 {%0,%1,%2,%3}, [%4];"
                 : "=r"(r.x), "=r"(r.y), "=r"(r.z), "=r"(r.w) : "r"(a));
}
__device__ __forceinline__ void ldsm_x2(uint2& r, uint32_t a){
    asm volatile("ldmatrix.sync.aligned.m8n8.x2.shared.b16 {%0,%1}, [%2];"
                 : "=r"(r.x), "=r"(r.y) : "r"(a));
}

__device__ __forceinline__ void cp16(uint32_t dst, const void* src, int sz){
    asm volatile("cp.async.ca.shared.global [%0], [%1], 16, %2;"
                 :: "r"(dst), "l"(src), "r"(sz) : "memory");
}
#define CPCOMMIT() asm volatile("cp.async.commit_group;" ::: "memory")
#define CPWAITG1() asm volatile("cp.async.wait_group 1;"  ::: "memory")

// ---------------- smem staging (rows of 128B = 64 fp16, XOR-swizzled 16B chunks) ----------
template<int NCHUNK>   // NCHUNK = rows*8
__device__ __forceinline__ void stage_tile(uint32_t sb, const __half* src, size_t ld){
    int tid = threadIdx.x;
    #pragma unroll
    for (int i = 0; i < (NCHUNK + 255)/256; i++){
        int idx = tid + i*256;
        if ((NCHUNK & 255) && idx >= NCHUNK) continue;
        int r = idx >> 3, c4 = idx & 7;
        cp16(sb + r*128 + ((uint32_t)(c4 ^ (r & 7)) << 4),
             src + (size_t)r*ld + (c4 << 3), 16);
    }
}

template<int NCHUNK>
__device__ __forceinline__ void stage_tile_vc(uint32_t sb, const __half* src, size_t ld, int vc){
    int tid = threadIdx.x;
    #pragma unroll
    for (int i = 0; i < (NCHUNK + 255)/256; i++){
        int idx = tid + i*256;
        if ((NCHUNK & 255) && idx >= NCHUNK) continue;
        int r = idx >> 3, c4 = idx & 7;
        int ok = (c4 < vc);
        cp16(sb + r*128 + ((uint32_t)(c4 ^ (r & 7)) << 4),
             src + (size_t)r*ld + ((ok ? c4 : 0) << 3), ok ? 16 : 0);
    }
}

// A slab from token rows of z (fp16), causal shift (token = seq0+r-shift; zeros if <0)
__device__ __forceinline__ void stage_tok(uint32_t sb, const __half* zb,
                                          int seq0, int shift, int col){
    int tid = threadIdx.x;
    #pragma unroll
    for (int i = 0; i < 4; i++){
        int idx = tid + i*256;
        int r = idx >> 3, c4 = idx & 7;
        int s = seq0 + r - shift;
        int sz = (s >= 0) ? 16 : 0;
        if (s < 0) s = 0;
        cp16(sb + r*128 + ((uint32_t)(c4 ^ (r & 7)) << 4),
             zb + (size_t)s*1024 + col + (c4 << 3), sz);
    }
}

// ---------------- fp16 ldmatrix fragment compute over one K=64 slab ----------------
template<int MT, int NT>
__device__ __forceinline__ void compLh(uint32_t sAu, uint32_t sBu, float4* acc,
                                       int mb0, int nb0, int lane){
    const int arow = (lane & 7) + ((lane >> 3) & 1)*8;
    const int khA  = (lane >> 4) & 1;
    uint32_t aB[MT]; int asw[MT];
    #pragma unroll
    for (int m = 0; m < MT; m++){
        int r = mb0 + m*16 + arow;
        aB[m] = sAu + r*128; asw[m] = r & 7;
    }
    constexpr int NP = NT >> 1;
    const int brow = ((lane >> 4) & 1)*8 + (lane & 7);
    const int khB  = (lane >> 3) & 1;
    uint32_t bB[NP > 0 ? NP : 1]; int bsw[NP > 0 ? NP : 1];
    #pragma unroll
    for (int p = 0; p < NP; p++){
        int r = nb0 + p*16 + brow;
        bB[p] = sBu + r*128; bsw[p] = r & 7;
    }
    uint32_t oB = 0; int osw = 0;
    if constexpr (NT & 1){
        int r = nb0 + (NT-1)*8 + (lane & 7);
        oB = sBu + r*128; osw = r & 7;
    }
    const int khO = (lane >> 3) & 1;
    #pragma unroll
    for (int kc = 0; kc < 4; kc++){
        uint4 a[MT];
        #pragma unroll
        for (int m = 0; m < MT; m++)
            ldsm_x4(a[m], aB[m] + (uint32_t)((((kc<<1)|khA) ^ asw[m]) << 4));
        #pragma unroll
        for (int p = 0; p < NP; p++){
            uint4 b;
            ldsm_x4(b, bB[p] + (uint32_t)((((kc<<1)|khB) ^ bsw[p]) << 4));
            #pragma unroll
            for (int m = 0; m < MT; m++){
                mma16(acc[m*NT + 2*p    ], a[m], make_uint2(b.x, b.y));
                mma16(acc[m*NT + 2*p + 1], a[m], make_uint2(b.z, b.w));
            }
        }
        if constexpr (NT & 1){
            uint2 b;
            ldsm_x2(b, oB + (uint32_t)((((kc<<1)|khO) ^ osw) << 4));
            #pragma unroll
            for (int m = 0; m < MT; m++)
                mma16(acc[m*NT + NT - 1], a[m], b);
        }
    }
}

template<int MT, int NT>
__device__ __forceinline__ void compL2h(uint32_t sAu, uint32_t sB1, uint32_t sB2,
                                        float4* acc1, float4* acc2,
                                        int mb0, int nb0, int lane){
    static_assert((NT & 1) == 0, "NT even");
    const int arow = (lane & 7) + ((lane >> 3) & 1)*8;
    const int khA  = (lane >> 4) & 1;
    uint32_t aB[MT]; int asw[MT];
    #pragma unroll
    for (int m = 0; m < MT; m++){
        int r = mb0 + m*16 + arow;
        aB[m] = sAu + r*128; asw[m] = r & 7;
    }
    constexpr int NP = NT >> 1;
    const int brow = ((lane >> 4) & 1)*8 + (lane & 7);
    const int khB  = (lane >> 3) & 1;
    uint32_t b1B[NP], b2B[NP]; int bsw[NP];
    #pragma unroll
    for (int p = 0; p < NP; p++){
        int r = nb0 + p*16 + brow;
        b1B[p] = sB1 + r*128; b2B[p] = sB2 + r*128; bsw[p] = r & 7;
    }
    #pragma unroll
    for (int kc = 0; kc < 4; kc++){
        uint4 a[MT];
        #pragma unroll
        for (int m = 0; m < MT; m++)
            ldsm_x4(a[m], aB[m] + (uint32_t)((((kc<<1)|khA) ^ asw[m]) << 4));
        #pragma unroll
        for (int p = 0; p < NP; p++){
            uint32_t off = (uint32_t)((((kc<<1)|khB) ^ bsw[p]) << 4);
            uint4 b1, b2;
            ldsm_x4(b1, b1B[p] + off);
            ldsm_x4(b2, b2B[p] + off);
            #pragma unroll
            for (int m = 0; m < MT; m++){
                mma16(acc1[m*NT + 2*p    ], a[m], make_uint2(b1.x, b1.y));
                mma16(acc1[m*NT + 2*p + 1], a[m], make_uint2(b1.z, b1.w));
                mma16(acc2[m*NT + 2*p    ], a[m], make_uint2(b2.x, b2.y));
                mma16(acc2[m*NT + 2*p + 1], a[m], make_uint2(b2.z, b2.w));
            }
        }
    }
}

// ---------------- weight fp16 conversion ----------------
__global__ void cvt_k(const float* p0, const float* p1, const float* p2, const float* p3,
                      const float* p4, const float* p5, const float* p6, const float* p7,
                      const float* p8, const float* p9, const float* p10, const float* p11,
                      const float* p12, const float* p13, const float* p14){
    const float* srcs[15] = {p0,p1,p2,p3,p4,p5,p6,p7,p8,p9,p10,p11,p12,p13,p14};
    const int sz4[15] = {65536,65536,8192,8192,16384,16384,90112,22528,8192,
                         90112,22528,8192,90112,8192,22528};
    const int off[15] = {W_FGW,W_GUW,W_FGA,W_GUA,W_FGB,W_GUB,W_FFGW,W_FFGA,W_FFGB,
                         W_FFFW,W_FFFA,W_FFFB,W_FFPW,W_FFPA,W_FFPB};
    int t = blockIdx.y;
    int i = blockIdx.x*256 + threadIdx.x;
    if (i >= sz4[t]) return;
    float4 v = ((const float4*)srcs[t])[i];
    __half2* dst = (__half2*)(g_wh + off[t]);
    dst[2*i]     = __floats2half2_rn(v.x, v.y);
    dst[2*i + 1] = __floats2half2_rn(v.z, v.w);
}

// ---------------- rmsnorm: h -> z (fp16 output) ----------------
__global__ __launch_bounds__(256)
void rms_k(const float* __restrict__ h, __half* __restrict__ z){
    int warp = threadIdx.x >> 5, lane = threadIdx.x & 31;
    size_t tok = (size_t)blockIdx.x*8 + warp;
    const float4* hr = (const float4*)(h + tok*1024);
    float4 v[8]; float ss = 0.f;
    #pragma unroll
    for (int j = 0; j < 8; j++){
        v[j] = hr[lane + 32*j];
        ss += v[j].x*v[j].x + v[j].y*v[j].y + v[j].z*v[j].z + v[j].w*v[j].w;
    }
    #pragma unroll
    for (int o = 16; o; o >>= 1) ss += __shfl_xor_sync(0xffffffffu, ss, o);
    float sc = rsqrtf(ss*(1.f/1024.f) + EPSRMS);
    __half2* zr = (__half2*)(z + tok*1024);
    #pragma unroll
    for (int j = 0; j < 8; j++){
        int p = lane + 32*j;
        zr[2*p]     = __floats2half2_rn(v[j].x*sc, v[j].y*sc);
        zr[2*p + 1] = __floats2half2_rn(v[j].z*sc, v[j].w*sc);
    }
}

// ---------------- low-rank projection, merged columns: P written directly ----------------
// grid (128). One CTA per token tile: full K, all 64 P columns.
// Slab q: half = q>>4 (0: z_t, 1: z_{t-1}), col = (q&15)*64. warp wm: M-rows wm*16..+15.
__global__ __launch_bounds__(256)
void p_k(const __half* __restrict__ z, __half* __restrict__ P,
         const __half* __restrict__ B1, const __half* __restrict__ B2,
         int halves, int ldB){
    extern __shared__ float sm[];
    uint32_t sb = smem_u32(sm);
    int tid = threadIdx.x, warp = tid >> 5, lane = tid & 31;
    int tile = blockIdx.x;
    int batch = tile >> 4, seq0 = (tile & 15) << 7;
    const __half* zb = z + (size_t)batch*2048*1024;
    int Q = halves << 4;

    auto fill = [&](int q, int buf){
        uint32_t aB = sb + (uint32_t)buf*24576u;
        uint32_t bB = aB + 16384u;
        int half = q >> 4, col = (q & 15) << 6;
        stage_tok(aB, zb, seq0, half, col);
        #pragma unroll
        for (int i = 0; i < 2; i++){
            int idx = tid + i*256;
            int r = idx >> 3, c4 = idx & 7;
            const __half* src = ((r < 32) ? B1 : B2)
                              + (size_t)(r & 31)*ldB + half*1024 + col + (c4 << 3);
            cp16(bB + r*128 + ((uint32_t)(c4 ^ (r & 7)) << 4), src, 16);
        }
    };
    fill(0, 0); CPCOMMIT();
    fill(1, 1); CPCOMMIT();

    float4 acc[8];
    #pragma unroll
    for (int i = 0; i < 8; i++) acc[i] = make_float4(0.f,0.f,0.f,0.f);

    for (int q = 0; q < Q; q++){
        CPWAITG1(); __syncthreads();
        uint32_t aB = sb + (uint32_t)(q % 3)*24576u;
        compLh<1,8>(aB, aB + 16384u, acc, warp*16, 0, lane);
        if (q + 2 < Q) fill(q + 2, (q + 2) % 3);
        CPCOMMIT();
    }

    int lr = lane >> 2, lc2 = (lane & 3)*2;
    size_t tok0 = (size_t)tile*128;
    #pragma unroll
    for (int n = 0; n < 8; n++){
        int r0 = warp*16 + lr;
        int col = n*8 + lc2;
        float4 d = acc[n];
        *(__half2*)(P + (tok0 + r0    )*64 + col) = __floats2half2_rn(d.x, d.y);
        *(__half2*)(P + (tok0 + r0 + 8)*64 + col) = __floats2half2_rn(d.z, d.w);
    }
}

// reduce partials -> fp16 (Pp only)
__global__ void pred_k(__half* __restrict__ dst, const float* __restrict__ src,
                       int nch, size_t cstride, int n4){
    int i = blockIdx.x*256 + threadIdx.x;
    if (i >= n4) return;
    float4 a = ((const float4*)src)[i];
    for (int c = 1; c < nch; c++){
        float4 v = ((const float4*)(src + (size_t)c*cstride))[i];
        a.x += v.x; a.y += v.y; a.z += v.z; a.w += v.w;
    }
    __half2* d2 = (__half2*)dst;
    d2[2*i]     = __floats2half2_rn(a.x, a.y);
    d2[2*i + 1] = __floats2half2_rn(a.z, a.w);
}

// ---------------- iteration main GEMM (4 weight slabs + 1 shared lowrank slab) ----------
__global__ __launch_bounds__(256)
void main_k(const __half* __restrict__ z, const __half* __restrict__ P,
            const float* __restrict__ hin, float* __restrict__ hout,
            const __half* __restrict__ Wg, const __half* __restrict__ Wu,
            const __half* __restrict__ Ag, const __half* __restrict__ Au){
    extern __shared__ float sm[];
    uint32_t sb = smem_u32(sm);
    int tid = threadIdx.x, warp = tid >> 5, lane = tid & 31;
    int wm = warp >> 1, wn = warp & 1;
    int tile = blockIdx.x, nb2 = blockIdx.y;
    int nblk = nb2 >> 1, nh = nb2 & 1;
    int batch = tile >> 4, seq0 = (tile & 15) << 7;
    const __half* zb = z + (size_t)batch*2048*1024;
    int shift = (nblk >= 4) ? 1 : 0;
    int colbase0 = (nblk & 3) << 8;
    size_t tok0 = (size_t)tile*128;
    int wrow0 = nblk*128 + nh*64;

    float4 accg[8], accu[8];
    #pragma unroll
    for (int i = 0; i < 8; i++){
        accg[i] = make_float4(0.f,0.f,0.f,0.f);
        accu[i] = make_float4(0.f,0.f,0.f,0.f);
    }

    auto fill = [&](int s, int buf){
        uint32_t aB = sb + (uint32_t)buf*32768u;
        uint32_t gB = aB + 16384u, uB = aB + 24576u;
        if (s < 4){
            stage_tok(aB, zb, seq0, shift, colbase0 + (s << 6));
            const __half* g = Wg + (size_t)wrow0*256 + (s << 6);
            const __half* u = Wu + (size_t)wrow0*256 + (s << 6);
            #pragma unroll
            for (int i = 0; i < 2; i++){
                int idx = tid + i*256;
                int r = idx >> 3, c4 = idx & 7;
                uint32_t so = r*128 + ((uint32_t)(c4 ^ (r & 7)) << 4);
                cp16(gB + so, g + (size_t)r*256 + (c4 << 3), 16);
                cp16(uB + so, u + (size_t)r*256 + (c4 << 3), 16);
            }
        } else {
            // shared lowrank slab: A = P[:,0:64]; Bg = [Ag|0], Bu = [0|Au]
            stage_tile<1024>(aB, P + tok0*64, 64);
            #pragma unroll
            for (int i = 0; i < 2; i++){
                int idx = tid + i*256;
                int r = idx >> 3, c4 = idx & 7;
                uint32_t so = r*128 + ((uint32_t)(c4 ^ (r & 7)) << 4);
                int glo = (c4 < 4);
                cp16(gB + so, Ag + (size_t)(wrow0 + r)*32 + ((glo ? c4 : 0) << 3), glo ? 16 : 0);
                cp16(uB + so, Au + (size_t)(wrow0 + r)*32 + ((glo ? 0 : (c4 - 4)) << 3), glo ? 0 : 16);
            }
        }
    };

    fill(0, 0); CPCOMMIT();
    fill(1, 1); CPCOMMIT();
    for (int s = 0; s < 5; s++){
        CPWAITG1(); __syncthreads();
        uint32_t aB = sb + (uint32_t)(s % 3)*32768u;
        compL2h<2,4>(aB, aB + 16384u, aB + 24576u, accg, accu, wm*32, wn*32, lane);
        if (s + 2 < 5) fill(s + 2, (s + 2) % 3);
        CPCOMMIT();
    }

    int lr = lane >> 2, lc2 = (lane & 3)*2;
    #pragma unroll
    for (int m = 0; m < 2; m++)
        #pragma unroll
        for (int n = 0; n < 4; n++){
            int r0 = wm*32 + m*16 + lr;
            int col = wrow0 + wn*32 + n*8 + lc2;
            float4 dg = accg[m*4 + n], du = accu[m*4 + n];
            size_t ta = tok0 + r0, tb = ta + 8;
            float2 ha = *(const float2*)(hin + ta*1024 + col);
            float2 hb = *(const float2*)(hin + tb*1024 + col);
            float2 oa, ob;
            oa.x = fmaf(sigm(dg.x), du.x, ha.x);
            oa.y = fmaf(sigm(dg.y), du.y, ha.y);
            ob.x = fmaf(sigm(dg.z), du.z, hb.x);
            ob.y = fmaf(sigm(dg.w), du.w, hb.y);
            *(float2*)(hout + ta*1024 + col) = oa;
            *(float2*)(hout + tb*1024 + col) = ob;
        }
}

// ---------------- fused ff GEMM: g phase -> park, f phase -> silu(g)*f -> g_ff ------------
__global__ __launch_bounds__(256)
void ff_k(const __half* __restrict__ z, const __half* __restrict__ P,
          const __half* __restrict__ Wg, const __half* __restrict__ Wf,
          const __half* __restrict__ Ag, const __half* __restrict__ Af){
    extern __shared__ float sm[];
    uint32_t sb = smem_u32(sm);
    float* park = sm + 116736/4;
    int tid = threadIdx.x, warp = tid >> 5, lane = tid & 31;
    int wm = warp >> 1, wn = warp & 1;
    int tile = blockIdx.x, nblk = blockIdx.y, nsub = blockIdx.z;
    int n0 = nblk*352 + nsub*176;
    size_t tok0 = (size_t)tile*128;

    float4 acc[22];
    #pragma unroll
    for (int i = 0; i < 22; i++) acc[i] = make_float4(0.f,0.f,0.f,0.f);

    auto fill = [&](int q, int buf){
        uint32_t aB = sb + (uint32_t)buf*38912u;
        uint32_t bB = aB + 16384u;
        int ph = (q >= 3), s = ph ? (q - 3) : q;
        const __half* W = ph ? Wf : Wg;
        if (s < 2){
            stage_tile<1024>(aB, z + tok0*1024 + nblk*128 + (s << 6), 1024);
            stage_tile<1408>(bB, W + (size_t)n0*128 + (s << 6), 128);
        } else {
            stage_tile<1024>(aB, P + tok0*64, 64);
            const __half* Alr = ph ? Af : Ag;
            #pragma unroll
            for (int i = 0; i < 6; i++){
                int idx = tid + i*256;
                if (idx >= 1408) continue;
                int r = idx >> 3, c4 = idx & 7;
                uint32_t so = bB + r*128 + ((uint32_t)(c4 ^ (r & 7)) << 4);
                int lo = (c4 < 4);
                int use = ph ? !lo : lo;             // g: chunks 0-3; f: chunks 4-7
                int cc = ph ? (c4 - 4) : c4;
                cp16(so, Alr + (size_t)(n0 + r)*32 + ((use ? cc : 0) << 3), use ? 16 : 0);
            }
        }
    };

    fill(0, 0); CPCOMMIT();
    fill(1, 1); CPCOMMIT();
    for (int q = 0; q < 6; q++){
        CPWAITG1();
        __syncthreads();
        uint32_t aB = sb + (uint32_t)(q % 3)*38912u;
        compLh<2,11>(aB, aB + 16384u, acc, wm*32, wn*88, lane);
        if (q == 2){
            float4* pk = (float4*)park + (size_t)tid*22;
            #pragma unroll
            for (int i = 0; i < 22; i++){
                pk[i] = acc[i];
                acc[i] = make_float4(0.f,0.f,0.f,0.f);
            }
        }
        if (q + 2 < 6) fill(q + 2, (q + 2) % 3);
        CPCOMMIT();
    }

    const float4* pk = (const float4*)park + (size_t)tid*22;
    int lr = lane >> 2, lc2 = (lane & 3)*2;
    #pragma unroll
    for (int m = 0; m < 2; m++)
        #pragma unroll
        for (int n = 0; n < 11; n++){
            int r0 = wm*32 + m*16 + lr;
            int col = n0 + wn*88 + n*8 + lc2;
            float4 f = acc[m*11 + n];
            float4 g = pk[m*11 + n];
            size_t ia = (tok0 + r0)*2816 + col;
            size_t ib = (tok0 + r0 + 8)*2816 + col;
            *(__half2*)(g_ff + ia) = __floats2half2_rn(g.x*sigm(g.x)*f.x, g.y*sigm(g.y)*f.y);
            *(__half2*)(g_ff + ib) = __floats2half2_rn(g.z*sigm(g.z)*f.z, g.w*sigm(g.w)*f.w);
        }
}

// ---------------- Pp partials: ff . ffp_B^T, K-split 8 x 352 (6 slabs, tail zfill) --------
__global__ __launch_bounds__(256)
void pp_k(const __half* __restrict__ ffpB){
    extern __shared__ float sm[];
    uint32_t sb = smem_u32(sm);
    int tid = threadIdx.x, warp = tid >> 5, lane = tid & 31;
    int wm = warp >> 1, wn = warp & 1;
    int tile = blockIdx.x, chunk = blockIdx.y;
    size_t tok0 = (size_t)tile*128;

    float4 acc[4];
    #pragma unroll
    for (int i = 0; i < 4; i++) acc[i] = make_float4(0.f,0.f,0.f,0.f);

    auto fill = [&](int s, int buf){
        uint32_t aB = sb + (uint32_t)buf*20480u;
        uint32_t bB = aB + 16384u;
        int vc = (s < 5) ? 8 : 4;                    // tail slab: 32 valid cols
        stage_tile_vc<1024>(aB, g_ff + tok0*2816 + chunk*352 + (s << 6), 2816, vc);
        stage_tile_vc<256>(bB, ffpB + chunk*352 + (s << 6), 2816, vc);
    };

    fill(0, 0); CPCOMMIT();
    fill(1, 1); CPCOMMIT();
    for (int s = 0; s < 6; s++){
        CPWAITG1(); __syncthreads();
        uint32_t aB = sb + (uint32_t)(s % 3)*20480u;
        compLh<2,2>(aB, aB + 16384u, acc, wm*32, wn*16, lane);
        if (s + 2 < 6) fill(s + 2, (s + 2) % 3);
        CPCOMMIT();
    }

    float* dst = g_part + (size_t)chunk*524288u;
    int lr = lane >> 2, lc2 = (lane & 3)*2;
    #pragma unroll
    for (int m = 0; m < 2; m++)
        #pragma unroll
        for (int n = 0; n < 2; n++){
            int r0 = wm*32 + m*16 + lr;
            int col = wn*16 + n*8 + lc2;
            float4 d = acc[m*2 + n];
            *(float2*)(dst + (tok0 + r0    )*32 + col) = make_float2(d.x, d.y);
            *(float2*)(dst + (tok0 + r0 + 8)*32 + col) = make_float2(d.z, d.w);
        }
}

// ---------------- out = h + ffp(ff) (5 full + tail + lowrank = 7 slabs) ----------------
__global__ __launch_bounds__(256)
void out_k(const float* __restrict__ hin, float* __restrict__ out,
           const __half* __restrict__ Wp, const __half* __restrict__ Ap){
    extern __shared__ float sm[];
    uint32_t sb = smem_u32(sm);
    int tid = threadIdx.x, warp = tid >> 5, lane = tid & 31;
    int wm = warp >> 1, wn = warp & 1;
    int tile = blockIdx.x, nb2 = blockIdx.y;
    int nblk = nb2 >> 1, nh = nb2 & 1;
    size_t tok0 = (size_t)tile*128;
    int wrow0 = nblk*128 + nh*64;

    float4 acc[8];
    #pragma unroll
    for (int i = 0; i < 8; i++) acc[i] = make_float4(0.f,0.f,0.f,0.f);

    auto fill = [&](int s, int buf){
        uint32_t aB = sb + (uint32_t)buf*24576u;
        uint32_t bB = aB + 16384u;
        if (s < 6){
            int vc = (s < 5) ? 8 : 4;
            stage_tile_vc<1024>(aB, g_ff + tok0*2816 + nblk*352 + (s << 6), 2816, vc);
            stage_tile_vc<512>(bB, Wp + (size_t)wrow0*352 + (s << 6), 352, vc);
        } else {
            stage_tile_vc<1024>(aB, g_Pp + tok0*32, 32, 4);
            stage_tile_vc<512>(bB, Ap + (size_t)wrow0*32, 32, 4);
        }
    };

    fill(0, 0); CPCOMMIT();
    fill(1, 1); CPCOMMIT();
    for (int s = 0; s < 7; s++){
        CPWAITG1(); __syncthreads();
        uint32_t aB = sb + (uint32_t)(s % 3)*24576u;
        compLh<2,4>(aB, aB + 16384u, acc, wm*32, wn*32, lane);
        if (s + 2 < 7) fill(s + 2, (s + 2) % 3);
        CPCOMMIT();
    }

    int lr = lane >> 2, lc2 = (lane & 3)*2;
    #pragma unroll
    for (int m = 0; m < 2; m++)
        #pragma unroll
        for (int n = 0; n < 4; n++){
            int r0 = wm*32 + m*16 + lr;
            int col = wrow0 + wn*32 + n*8 + lc2;
            float4 d = acc[m*4 + n];
            size_t ta = tok0 + r0, tb = ta + 8;
            float2 ha = *(const float2*)(hin + ta*1024 + col);
            float2 hb = *(const float2*)(hin + tb*1024 + col);
            *(float2*)(out + ta*1024 + col) = make_float2(ha.x + d.x, ha.y + d.y);
            *(float2*)(out + tb*1024 + col) = make_float2(hb.x + d.z, hb.y + d.w);
        }
}

// ---------------- launcher ----------------
template <typename T>
static void* symaddr(const T& s){
    void* p = nullptr;
    cudaGetSymbolAddress(&p, s);
    return p;
}

extern "C" void kernel_launch(void* const* d_in, const int* in_sizes, int n_in,
                              void* d_out, int out_size) {
    const float* x     = (const float*)d_in[0];
    const float* fg_W  = (const float*)d_in[1];
    const float* fg_A  = (const float*)d_in[2];
    const float* fg_B  = (const float*)d_in[3];
    const float* gu_W  = (const float*)d_in[4];
    const float* gu_A  = (const float*)d_in[5];
    const float* gu_B  = (const float*)d_in[6];
    const float* ffg_W = (const float*)d_in[7];
    const float* ffg_A = (const float*)d_in[8];
    const float* ffg_B = (const float*)d_in[9];
    const float* fff_W = (const float*)d_in[10];
    const float* fff_A = (const float*)d_in[11];
    const float* fff_B = (const float*)d_in[12];
    const float* ffp_W = (const float*)d_in[13];
    const float* ffp_A = (const float*)d_in[14];
    const float* ffp_B = (const float*)d_in[15];
    float* out = (float*)d_out;

    __half* z    = (__half*)symaddr(g_z);
    float*  h0   = (float*)symaddr(g_h0);
    float*  h1   = (float*)symaddr(g_h1);
    __half* P    = (__half*)symaddr(g_P);
    __half* Pp   = (__half*)symaddr(g_Pp);
    float*  part = (float*)symaddr(g_part);
    __half* wh   = (__half*)symaddr(g_wh);

    const int SM_P    = 3*24576;            // 72 KB
    const int SM_MAIN = 3*32768;            // 96 KB
    const int SM_FF   = 3*38912 + 90112;    // ~202 KB (3-stage + park)
    const int SM_PP   = 3*20480;            // 60 KB
    const int SM_OUT  = 3*24576;            // 72 KB
    cudaFuncSetAttribute(p_k,    cudaFuncAttributeMaxDynamicSharedMemorySize, SM_P);
    cudaFuncSetAttribute(main_k, cudaFuncAttributeMaxDynamicSharedMemorySize, SM_MAIN);
    cudaFuncSetAttribute(ff_k,   cudaFuncAttributeMaxDynamicSharedMemorySize, SM_FF);
    cudaFuncSetAttribute(pp_k,   cudaFuncAttributeMaxDynamicSharedMemorySize, SM_PP);
    cudaFuncSetAttribute(out_k,  cudaFuncAttributeMaxDynamicSharedMemorySize, SM_OUT);

    cvt_k<<<dim3(352, 15), 256>>>(fg_W, gu_W, fg_A, gu_A, fg_B, gu_B,
                                  ffg_W, ffg_A, ffg_B, fff_W, fff_A, fff_B,
                                  ffp_W, ffp_A, ffp_B);

    const float* hcur = x;
    float* bufs[2] = {h0, h1};
    for (int it = 0; it < 4; it++){
        float* hnext = bufs[it & 1];
        rms_k<<<2048, 256>>>(hcur, z);
        p_k<<<128, 256, SM_P>>>(z, P, wh + W_FGB, wh + W_GUB, 2, 2048);
        main_k<<<dim3(128, 16), 256, SM_MAIN>>>(z, P, hcur, hnext,
                                                wh + W_FGW, wh + W_GUW,
                                                wh + W_FGA, wh + W_GUA);
        hcur = hnext;
    }
    rms_k<<<2048, 256>>>(hcur, z);
    p_k<<<128, 256, SM_P>>>(z, P, wh + W_FFGB, wh + W_FFFB, 1, 1024);
    ff_k<<<dim3(128, 8, 2), 256, SM_FF>>>(z, P, wh + W_FFGW, wh + W_FFFW,
                                          wh + W_FFGA, wh + W_FFFA);
    pp_k<<<dim3(128, 8), 256, SM_PP>>>(wh + W_FFPB);
    pred_k<<<512, 256>>>(Pp, part, 8, (size_t)524288, 131072);
    out_k<<<dim3(128, 16), 256, SM_OUT>>>(hcur, out, wh + W_FFPW, wh + W_FFPA);
}